// round 3
// baseline (speedup 1.0000x reference)
#include <cuda_runtime.h>
#include <cuda_bf16.h>
#include <cstdint>

#define N_USERS 50000
#define D 128
#define N_EDGES 800000
#define SCAN_THREADS 1024

// -------- device scratch (no cudaMalloc allowed) --------
__device__ float g_weighted[N_USERS * D];     // emb @ W
__device__ int   g_counts[N_USERS];           // edges per destination row
__device__ int   g_row_start[N_USERS];        // exclusive prefix sum
__device__ int   g_cursor[N_USERS];           // scatter cursors
__device__ int2  g_epacked[N_EDGES];          // (col, val_bits) sorted by dest row

// ---------------------------------------------------------------------------
// Kernel 1: weighted = user_emb @ W   using packed fma.rn.f32x2 (FFMA2)
// W staged in 64 KB smem. 8 warps/block, 8 rows/warp, lane covers 4 cols.
// ---------------------------------------------------------------------------
__global__ __launch_bounds__(256) void gemm_kernel(
    const float* __restrict__ emb,
    const float* __restrict__ W,
    float* __restrict__ out)
{
    extern __shared__ float Ws[];   // [D*D] = 64 KB

    {
        const float4* Wg4 = reinterpret_cast<const float4*>(W);
        float4* Ws4 = reinterpret_cast<float4*>(Ws);
        #pragma unroll
        for (int i = 0; i < (D * D / 4) / 256; i++)
            Ws4[i * 256 + threadIdx.x] = Wg4[i * 256 + threadIdx.x];
    }
    __syncthreads();

    const int warp = threadIdx.x >> 5;
    const int lane = threadIdx.x & 31;
    const int row0 = (blockIdx.x * 8 + warp) * 8;
    if (row0 >= N_USERS) return;
    const int colbase = lane * 4;
    const bool full = (row0 + 8 <= N_USERS);

    unsigned long long accA[8], accB[8];      // f32x2 pairs: cols [0,1] and [2,3]
    #pragma unroll
    for (int r = 0; r < 8; r++) { accA[r] = 0ull; accB[r] = 0ull; }

    const float4* erow[8];
    #pragma unroll
    for (int r = 0; r < 8; r++) {
        int rr = full ? (row0 + r) : min(row0 + r, N_USERS - 1);
        erow[r] = reinterpret_cast<const float4*>(emb + (size_t)rr * D);
    }

    #pragma unroll 2
    for (int kk = 0; kk < D / 4; kk++) {
        float4 a[8];
        #pragma unroll
        for (int r = 0; r < 8; r++) a[r] = erow[r][kk];

        #pragma unroll
        for (int j = 0; j < 4; j++) {
            const int k = kk * 4 + j;
            const unsigned long long* wp =
                reinterpret_cast<const unsigned long long*>(Ws + k * D + colbase);
            unsigned long long wlo = wp[0];
            unsigned long long whi = wp[1];
            #pragma unroll
            for (int r = 0; r < 8; r++) {
                float b = (j == 0) ? a[r].x : (j == 1) ? a[r].y
                        : (j == 2) ? a[r].z : a[r].w;
                unsigned long long bs;
                asm("mov.b64 %0, {%1, %1};" : "=l"(bs) : "r"(__float_as_uint(b)));
                asm("fma.rn.f32x2 %0, %1, %2, %0;" : "+l"(accA[r]) : "l"(bs), "l"(wlo));
                asm("fma.rn.f32x2 %0, %1, %2, %0;" : "+l"(accB[r]) : "l"(bs), "l"(whi));
            }
        }
    }

    #pragma unroll
    for (int r = 0; r < 8; r++) {
        if (full || (row0 + r) < N_USERS) {
            float x, y, z, w;
            asm("mov.b64 {%0, %1}, %2;" : "=f"(x), "=f"(y) : "l"(accA[r]));
            asm("mov.b64 {%0, %1}, %2;" : "=f"(z), "=f"(w) : "l"(accB[r]));
            *reinterpret_cast<float4*>(out + (size_t)(row0 + r) * D + colbase) =
                make_float4(x, y, z, w);
        }
    }
}

// ---------------------------------------------------------------------------
// CSR build
// ---------------------------------------------------------------------------
__global__ void zero_counts_kernel(int* __restrict__ counts)
{
    int i = blockIdx.x * blockDim.x + threadIdx.x;
    if (i < N_USERS) counts[i] = 0;
}

__global__ void count_kernel(const int* __restrict__ rows, int* __restrict__ counts)
{
    int e = blockIdx.x * blockDim.x + threadIdx.x;
    if (e < N_EDGES) atomicAdd(&counts[rows[e]], 1);
}

// Single-block scan: 1024 threads, each owns a contiguous chunk of counts.
__global__ __launch_bounds__(SCAN_THREADS) void scan_kernel(
    const int* __restrict__ counts,
    int* __restrict__ row_start,
    int* __restrict__ cursor)
{
    __shared__ int partial[SCAN_THREADS];
    const int C = (N_USERS + SCAN_THREADS - 1) / SCAN_THREADS;  // 49
    const int t = threadIdx.x;
    const int base = t * C;

    int s = 0;
    for (int i = 0; i < C; i++) {
        int idx = base + i;
        if (idx < N_USERS) s += counts[idx];
    }
    partial[t] = s;
    __syncthreads();

    // Hillis-Steele inclusive scan over 1024 partials
    for (int off = 1; off < SCAN_THREADS; off <<= 1) {
        int v = partial[t];
        int add = (t >= off) ? partial[t - off] : 0;
        __syncthreads();
        partial[t] = v + add;
        __syncthreads();
    }

    int run = (t == 0) ? 0 : partial[t - 1];
    for (int i = 0; i < C; i++) {
        int idx = base + i;
        if (idx < N_USERS) {
            row_start[idx] = run;
            cursor[idx]    = run;
            run += counts[idx];
        }
    }
}

__global__ void scatter_kernel(
    const int* __restrict__ rows,
    const int* __restrict__ cols,
    const float* __restrict__ vals,
    int* __restrict__ cursor,
    int2* __restrict__ epacked)
{
    int e = blockIdx.x * blockDim.x + threadIdx.x;
    if (e >= N_EDGES) return;
    int r = rows[e];
    int pos = atomicAdd(&cursor[r], 1);
    epacked[pos] = make_int2(cols[e], __float_as_int(vals[e]));
}

// ---------------------------------------------------------------------------
// Accumulate: one warp per destination row.
// out[r] = emb[r] + sum_e vals[e] * weighted[cols[e]]
// ---------------------------------------------------------------------------
__global__ __launch_bounds__(256) void accum_kernel(
    const float* __restrict__ emb,
    const float* __restrict__ weighted,
    const int* __restrict__ row_start,
    const int* __restrict__ counts,
    const int2* __restrict__ epacked,
    float* __restrict__ out)
{
    const int warp = threadIdx.x >> 5;
    const int lane = threadIdx.x & 31;
    const int row = blockIdx.x * 8 + warp;
    if (row >= N_USERS) return;

    const int start = __ldg(row_start + row);
    const int n     = __ldg(counts + row);
    const int end   = start + n;
    const int coff  = lane * 4;

    float4 acc = make_float4(0.f, 0.f, 0.f, 0.f);

    int i = start;
    for (; i + 1 < end; i += 2) {
        int2 e0 = __ldg(epacked + i);
        int2 e1 = __ldg(epacked + i + 1);
        float4 w0 = *reinterpret_cast<const float4*>(weighted + (size_t)e0.x * D + coff);
        float4 w1 = *reinterpret_cast<const float4*>(weighted + (size_t)e1.x * D + coff);
        float v0 = __int_as_float(e0.y);
        float v1 = __int_as_float(e1.y);
        acc.x += v0 * w0.x; acc.y += v0 * w0.y; acc.z += v0 * w0.z; acc.w += v0 * w0.w;
        acc.x += v1 * w1.x; acc.y += v1 * w1.y; acc.z += v1 * w1.z; acc.w += v1 * w1.w;
    }
    if (i < end) {
        int2 e0 = __ldg(epacked + i);
        float4 w0 = *reinterpret_cast<const float4*>(weighted + (size_t)e0.x * D + coff);
        float v0 = __int_as_float(e0.y);
        acc.x += v0 * w0.x; acc.y += v0 * w0.y; acc.z += v0 * w0.z; acc.w += v0 * w0.w;
    }

    float4 e = *reinterpret_cast<const float4*>(emb + (size_t)row * D + coff);
    *reinterpret_cast<float4*>(out + (size_t)row * D + coff) =
        make_float4(e.x + acc.x, e.y + acc.y, e.z + acc.z, e.w + acc.w);
}

// ---------------------------------------------------------------------------
// Launch
// ---------------------------------------------------------------------------
extern "C" void kernel_launch(void* const* d_in, const int* in_sizes, int n_in,
                              void* d_out, int out_size)
{
    const float* user_emb = (const float*)d_in[0];
    const float* social_w = (const float*)d_in[1];
    const int*   rows     = (const int*)d_in[2];
    const int*   cols     = (const int*)d_in[3];
    const float* vals     = (const float*)d_in[4];
    float*       out      = (float*)d_out;

    float* weighted;  cudaGetSymbolAddress((void**)&weighted,  g_weighted);
    int*   counts;    cudaGetSymbolAddress((void**)&counts,    g_counts);
    int*   row_start; cudaGetSymbolAddress((void**)&row_start, g_row_start);
    int*   cursor;    cudaGetSymbolAddress((void**)&cursor,    g_cursor);
    int2*  epacked;   cudaGetSymbolAddress((void**)&epacked,   g_epacked);

    // CSR build (independent of GEMM result)
    zero_counts_kernel<<<(N_USERS + 255) / 256, 256>>>(counts);
    count_kernel<<<(N_EDGES + 255) / 256, 256>>>(rows, counts);
    scan_kernel<<<1, SCAN_THREADS>>>(counts, row_start, cursor);
    scatter_kernel<<<(N_EDGES + 255) / 256, 256>>>(rows, cols, vals, cursor, epacked);

    // GEMM: weighted = user_emb @ W
    {
        const int smem_bytes = D * D * sizeof(float);  // 65536
        cudaFuncSetAttribute(gemm_kernel,
                             cudaFuncAttributeMaxDynamicSharedMemorySize, smem_bytes);
        int nblk = (N_USERS + 63) / 64;
        gemm_kernel<<<nblk, 256, smem_bytes>>>(user_emb, social_w, weighted);
    }

    // Fused neighbor-sum + residual
    accum_kernel<<<(N_USERS + 7) / 8, 256>>>(
        user_emb, weighted, row_start, counts, epacked, out);
}

// round 4
// speedup vs baseline: 1.2594x; 1.2594x over previous
#include <cuda_runtime.h>
#include <cuda_fp16.h>
#include <cstdint>

#define N_USERS 50000
#define D 128
#define N_EDGES 800000

// Scratch: weighted = user_emb @ W stored in fp16 (halves edge-gather traffic)
__device__ __half g_weighted_h[N_USERS * D];

// ---------------------------------------------------------------------------
// Kernel 1: weighted_h = fp16(user_emb @ W);  out = user_emb (residual init)
// W staged in 64 KB smem. 8 warps/block, 8 rows/warp, lane covers 4 cols.
// Mainloop uses packed fma.rn.f32x2.
// ---------------------------------------------------------------------------
__global__ __launch_bounds__(256) void gemm_kernel(
    const float* __restrict__ emb,
    const float* __restrict__ W,
    __half* __restrict__ wout,      // [N_USERS, D] fp16
    float* __restrict__ resout)     // [N_USERS, D] fp32 residual init
{
    extern __shared__ float Ws[];   // [D*D] = 64 KB

    {
        const float4* Wg4 = reinterpret_cast<const float4*>(W);
        float4* Ws4 = reinterpret_cast<float4*>(Ws);
        #pragma unroll
        for (int i = 0; i < (D * D / 4) / 256; i++)
            Ws4[i * 256 + threadIdx.x] = Wg4[i * 256 + threadIdx.x];
    }
    __syncthreads();

    const int warp = threadIdx.x >> 5;
    const int lane = threadIdx.x & 31;
    const int row0 = (blockIdx.x * 8 + warp) * 8;
    if (row0 >= N_USERS) return;
    const int colbase = lane * 4;
    const bool full = (row0 + 8 <= N_USERS);

    unsigned long long accA[8], accB[8];   // f32x2 pairs: cols [0,1] and [2,3]
    #pragma unroll
    for (int r = 0; r < 8; r++) { accA[r] = 0ull; accB[r] = 0ull; }

    const float4* erow[8];
    #pragma unroll
    for (int r = 0; r < 8; r++) {
        int rr = full ? (row0 + r) : min(row0 + r, N_USERS - 1);
        erow[r] = reinterpret_cast<const float4*>(emb + (size_t)rr * D);
    }

    #pragma unroll 2
    for (int kk = 0; kk < D / 4; kk++) {
        float4 a[8];
        #pragma unroll
        for (int r = 0; r < 8; r++) a[r] = erow[r][kk];

        // residual init: this warp's lanes collectively cover cols [0,128) of
        // each of its 8 rows over the kk loop; lane 'kk-slice' writes a[r]
        // when kk maps to this lane? No — each lane loads the SAME kk slice
        // for its rows, so have lane==kk write it:
        if ((unsigned)kk == (unsigned)lane) {
            #pragma unroll
            for (int r = 0; r < 8; r++) {
                if (full || (row0 + r) < N_USERS)
                    *reinterpret_cast<float4*>(resout + (size_t)(row0 + r) * D + kk * 4) = a[r];
            }
        }

        #pragma unroll
        for (int j = 0; j < 4; j++) {
            const int k = kk * 4 + j;
            const unsigned long long* wp =
                reinterpret_cast<const unsigned long long*>(Ws + k * D + colbase);
            unsigned long long wlo = wp[0];
            unsigned long long whi = wp[1];
            #pragma unroll
            for (int r = 0; r < 8; r++) {
                float b = (j == 0) ? a[r].x : (j == 1) ? a[r].y
                        : (j == 2) ? a[r].z : a[r].w;
                unsigned long long bs;
                asm("mov.b64 %0, {%1, %1};" : "=l"(bs) : "r"(__float_as_uint(b)));
                asm("fma.rn.f32x2 %0, %1, %2, %0;" : "+l"(accA[r]) : "l"(bs), "l"(wlo));
                asm("fma.rn.f32x2 %0, %1, %2, %0;" : "+l"(accB[r]) : "l"(bs), "l"(whi));
            }
        }
    }

    #pragma unroll
    for (int r = 0; r < 8; r++) {
        if (full || (row0 + r) < N_USERS) {
            float x, y, z, w;
            asm("mov.b64 {%0, %1}, %2;" : "=f"(x), "=f"(y) : "l"(accA[r]));
            asm("mov.b64 {%0, %1}, %2;" : "=f"(z), "=f"(w) : "l"(accB[r]));
            __half2 h0 = __floats2half2_rn(x, y);
            __half2 h1 = __floats2half2_rn(z, w);
            uint2 pk;
            pk.x = *reinterpret_cast<unsigned*>(&h0);
            pk.y = *reinterpret_cast<unsigned*>(&h1);
            *reinterpret_cast<uint2*>(wout + (size_t)(row0 + r) * D + colbase) = pk;
        }
    }
}

// ---------------------------------------------------------------------------
// Kernel 2: out[rows[e]] += vals[e] * weighted_h[cols[e]]
// One warp per edge; lane covers 4 halves (8B load) -> red.global.add.v4.f32
// ---------------------------------------------------------------------------
__global__ __launch_bounds__(256) void edge_kernel(
    const int* __restrict__ rows,
    const int* __restrict__ cols,
    const float* __restrict__ vals,
    const __half* __restrict__ weighted,
    float* __restrict__ out)
{
    const int warp = (blockIdx.x * blockDim.x + threadIdx.x) >> 5;
    const int lane = threadIdx.x & 31;
    if (warp >= N_EDGES) return;

    const int   r = __ldg(rows + warp);
    const int   c = __ldg(cols + warp);
    const float v = __ldg(vals + warp);

    uint2 pk = *reinterpret_cast<const uint2*>(weighted + (size_t)c * D + lane * 4);
    __half2 h0 = *reinterpret_cast<__half2*>(&pk.x);
    __half2 h1 = *reinterpret_cast<__half2*>(&pk.y);
    float2 f0 = __half22float2(h0);
    float2 f1 = __half22float2(h1);

    float px = v * f0.x, py = v * f0.y, pz = v * f1.x, pw = v * f1.y;

    float* dst = out + (size_t)r * D + lane * 4;
    asm volatile("red.global.add.v4.f32 [%0], {%1,%2,%3,%4};"
                 :: "l"(dst), "f"(px), "f"(py), "f"(pz), "f"(pw)
                 : "memory");
}

// ---------------------------------------------------------------------------
// Launch
// Inputs: user_emb [50000*128] f32, social_weight [128*128] f32,
//         rows [800000] i32, cols [800000] i32, vals [800000] f32
// Output: [50000*128] f32
// ---------------------------------------------------------------------------
extern "C" void kernel_launch(void* const* d_in, const int* in_sizes, int n_in,
                              void* d_out, int out_size)
{
    const float* user_emb = (const float*)d_in[0];
    const float* social_w = (const float*)d_in[1];
    const int*   rows     = (const int*)d_in[2];
    const int*   cols     = (const int*)d_in[3];
    const float* vals     = (const float*)d_in[4];
    float*       out      = (float*)d_out;

    __half* weighted = nullptr;
    cudaGetSymbolAddress((void**)&weighted, g_weighted_h);

    // 1. weighted_h = fp16(user_emb @ W); out = user_emb
    {
        const int smem_bytes = D * D * sizeof(float);  // 65536
        cudaFuncSetAttribute(gemm_kernel,
                             cudaFuncAttributeMaxDynamicSharedMemorySize, smem_bytes);
        int nblk = (N_USERS + 63) / 64;                // 8 warps x 8 rows
        gemm_kernel<<<nblk, 256, smem_bytes>>>(user_emb, social_w, weighted, out);
    }

    // 2. scatter-add edges (RED v4.f32, no return)
    {
        long long total_threads = (long long)N_EDGES * 32;
        int nblk = (int)((total_threads + 255) / 256);
        edge_kernel<<<nblk, 256>>>(rows, cols, vals, weighted, out);
    }
}

// round 5
// speedup vs baseline: 1.3673x; 1.0857x over previous
#include <cuda_runtime.h>
#include <cuda_fp16.h>
#include <cstdint>

#define N_USERS 50000
#define D 128
#define N_EDGES 800000
#define E_PER_WARP 8

// Scratch: weighted = user_emb @ W stored in fp16 (halves edge-gather traffic)
__device__ __half g_weighted_h[N_USERS * D];

// ---------------------------------------------------------------------------
// Kernel 1: weighted_h = fp16(user_emb @ W);  out = user_emb (residual init)
// W staged in 64 KB smem. 8 warps/block, 8 rows/warp, lane covers 4 cols.
// Mainloop uses packed fma.rn.f32x2.
// ---------------------------------------------------------------------------
__global__ __launch_bounds__(256) void gemm_kernel(
    const float* __restrict__ emb,
    const float* __restrict__ W,
    __half* __restrict__ wout,      // [N_USERS, D] fp16
    float* __restrict__ resout)     // [N_USERS, D] fp32 residual init
{
    extern __shared__ float Ws[];   // [D*D] = 64 KB

    {
        const float4* Wg4 = reinterpret_cast<const float4*>(W);
        float4* Ws4 = reinterpret_cast<float4*>(Ws);
        #pragma unroll
        for (int i = 0; i < (D * D / 4) / 256; i++)
            Ws4[i * 256 + threadIdx.x] = Wg4[i * 256 + threadIdx.x];
    }
    __syncthreads();

    const int warp = threadIdx.x >> 5;
    const int lane = threadIdx.x & 31;
    const int row0 = (blockIdx.x * 8 + warp) * 8;
    if (row0 >= N_USERS) return;
    const int colbase = lane * 4;
    const bool full = (row0 + 8 <= N_USERS);

    unsigned long long accA[8], accB[8];   // f32x2 pairs: cols [0,1] and [2,3]
    #pragma unroll
    for (int r = 0; r < 8; r++) { accA[r] = 0ull; accB[r] = 0ull; }

    const float4* erow[8];
    #pragma unroll
    for (int r = 0; r < 8; r++) {
        int rr = full ? (row0 + r) : min(row0 + r, N_USERS - 1);
        erow[r] = reinterpret_cast<const float4*>(emb + (size_t)rr * D);
    }

    #pragma unroll 2
    for (int kk = 0; kk < D / 4; kk++) {
        float4 a[8];
        #pragma unroll
        for (int r = 0; r < 8; r++) a[r] = erow[r][kk];

        // residual init: lane kk owns the kk-th float4 slice of each row
        if ((unsigned)kk == (unsigned)lane) {
            #pragma unroll
            for (int r = 0; r < 8; r++) {
                if (full || (row0 + r) < N_USERS)
                    *reinterpret_cast<float4*>(resout + (size_t)(row0 + r) * D + kk * 4) = a[r];
            }
        }

        #pragma unroll
        for (int j = 0; j < 4; j++) {
            const int k = kk * 4 + j;
            const unsigned long long* wp =
                reinterpret_cast<const unsigned long long*>(Ws + k * D + colbase);
            unsigned long long wlo = wp[0];
            unsigned long long whi = wp[1];
            #pragma unroll
            for (int r = 0; r < 8; r++) {
                float b = (j == 0) ? a[r].x : (j == 1) ? a[r].y
                        : (j == 2) ? a[r].z : a[r].w;
                unsigned long long bs;
                asm("mov.b64 %0, {%1, %1};" : "=l"(bs) : "r"(__float_as_uint(b)));
                asm("fma.rn.f32x2 %0, %1, %2, %0;" : "+l"(accA[r]) : "l"(bs), "l"(wlo));
                asm("fma.rn.f32x2 %0, %1, %2, %0;" : "+l"(accB[r]) : "l"(bs), "l"(whi));
            }
        }
    }

    #pragma unroll
    for (int r = 0; r < 8; r++) {
        if (full || (row0 + r) < N_USERS) {
            float x, y, z, w;
            asm("mov.b64 {%0, %1}, %2;" : "=f"(x), "=f"(y) : "l"(accA[r]));
            asm("mov.b64 {%0, %1}, %2;" : "=f"(z), "=f"(w) : "l"(accB[r]));
            __half2 h0 = __floats2half2_rn(x, y);
            __half2 h1 = __floats2half2_rn(z, w);
            uint2 pk;
            pk.x = *reinterpret_cast<unsigned*>(&h0);
            pk.y = *reinterpret_cast<unsigned*>(&h1);
            *reinterpret_cast<uint2*>(wout + (size_t)(row0 + r) * D + colbase) = pk;
        }
    }
}

// ---------------------------------------------------------------------------
// Kernel 2: out[rows[e]] += vals[e] * weighted_h[cols[e]]
// 8 edges per warp: lanes 0-7 load edge metadata, shfl-broadcast, then the
// warp issues 8 independent gathers (MLP=8) followed by 8 REDs.
// N_EDGES = 800000 = 100000 warps * 8 exactly; no tail.
// ---------------------------------------------------------------------------
__global__ __launch_bounds__(256) void edge_kernel(
    const int* __restrict__ rows,
    const int* __restrict__ cols,
    const float* __restrict__ vals,
    const __half* __restrict__ weighted,
    float* __restrict__ out)
{
    const int warp = (blockIdx.x * blockDim.x + threadIdx.x) >> 5;
    const int lane = threadIdx.x & 31;
    const long long e0 = (long long)warp * E_PER_WARP;
    if (e0 >= N_EDGES) return;

    // lane (i & 7) holds edge e0+i metadata (all lanes load; 32B sector, coalesced)
    const int eidx = (int)e0 + (lane & (E_PER_WARP - 1));
    int   ri = __ldg(rows + eidx);
    int   ci = __ldg(cols + eidx);
    float vi = __ldg(vals + eidx);

    // 8 independent gathers in flight
    uint2 pk[E_PER_WARP];
    #pragma unroll
    for (int i = 0; i < E_PER_WARP; i++) {
        int c = __shfl_sync(0xffffffffu, ci, i);
        pk[i] = *reinterpret_cast<const uint2*>(weighted + (size_t)c * D + lane * 4);
    }

    #pragma unroll
    for (int i = 0; i < E_PER_WARP; i++) {
        int   r = __shfl_sync(0xffffffffu, ri, i);
        float v = __shfl_sync(0xffffffffu, vi, i);
        __half2 h0 = *reinterpret_cast<__half2*>(&pk[i].x);
        __half2 h1 = *reinterpret_cast<__half2*>(&pk[i].y);
        float2 f0 = __half22float2(h0);
        float2 f1 = __half22float2(h1);
        float px = v * f0.x, py = v * f0.y, pz = v * f1.x, pw = v * f1.y;
        float* dst = out + (size_t)r * D + lane * 4;
        asm volatile("red.global.add.v4.f32 [%0], {%1,%2,%3,%4};"
                     :: "l"(dst), "f"(px), "f"(py), "f"(pz), "f"(pw)
                     : "memory");
    }
}

// ---------------------------------------------------------------------------
// Launch
// Inputs: user_emb [50000*128] f32, social_weight [128*128] f32,
//         rows [800000] i32, cols [800000] i32, vals [800000] f32
// Output: [50000*128] f32
// ---------------------------------------------------------------------------
extern "C" void kernel_launch(void* const* d_in, const int* in_sizes, int n_in,
                              void* d_out, int out_size)
{
    const float* user_emb = (const float*)d_in[0];
    const float* social_w = (const float*)d_in[1];
    const int*   rows     = (const int*)d_in[2];
    const int*   cols     = (const int*)d_in[3];
    const float* vals     = (const float*)d_in[4];
    float*       out      = (float*)d_out;

    __half* weighted = nullptr;
    cudaGetSymbolAddress((void**)&weighted, g_weighted_h);

    // 1. weighted_h = fp16(user_emb @ W); out = user_emb
    {
        const int smem_bytes = D * D * sizeof(float);  // 65536
        cudaFuncSetAttribute(gemm_kernel,
                             cudaFuncAttributeMaxDynamicSharedMemorySize, smem_bytes);
        int nblk = (N_USERS + 63) / 64;                // 8 warps x 8 rows
        gemm_kernel<<<nblk, 256, smem_bytes>>>(user_emb, social_w, weighted, out);
    }

    // 2. scatter-add edges, 8 edges per warp
    {
        int nwarps = N_EDGES / E_PER_WARP;             // 100000
        int nblk = (nwarps * 32 + 255) / 256;          // 12500
        edge_kernel<<<nblk, 256>>>(rows, cols, vals, weighted, out);
    }
}

// round 6
// speedup vs baseline: 1.8150x; 1.3275x over previous
#include <cuda_runtime.h>
#include <cuda_fp16.h>
#include <cstdint>

#define N_USERS 50000
#define D 128
#define N_EDGES 800000
#define E_PER_WARP 8
#define WS_STRIDE 132   // padded smem stride (bank-conflict-free B fetch)

// Scratch: weighted = user_emb @ W stored in fp16 (halves edge-gather traffic)
__device__ __half g_weighted_h[N_USERS * D];

// ---------------------------------------------------------------------------
// Kernel 1: weighted_h = fp16(user_emb @ W) via mma.sync tf32; out = user_emb.
// Block = 256 threads (8 warps); each warp computes 16 rows x 128 cols.
// W pre-converted to tf32 in padded smem. 16 k-steps x 16 n-tiles of
// m16n8k8 mma per warp.
// ---------------------------------------------------------------------------
__global__ __launch_bounds__(256) void gemm_kernel(
    const float* __restrict__ emb,
    const float* __restrict__ W,
    __half* __restrict__ wout,      // [N_USERS, D] fp16
    float* __restrict__ resout)     // [N_USERS, D] fp32 residual init
{
    extern __shared__ float Ws[];   // [D][WS_STRIDE] tf32 bits
    const int tid = threadIdx.x;

    // ---- residual init: this block's 128 rows, out = emb (float4) ----
    {
        const int rowbase = blockIdx.x * 128;
        const float4* src = reinterpret_cast<const float4*>(emb);
        float4* dst = reinterpret_cast<float4*>(resout);
        #pragma unroll
        for (int i = 0; i < 16; i++) {              // 128 rows * 32 f4 = 4096
            int idx = i * 256 + tid;
            int r = rowbase + (idx >> 5);
            if (r < N_USERS) {
                size_t o = (size_t)r * 32 + (idx & 31);
                dst[o] = src[o];
            }
        }
    }

    // ---- W -> smem, pre-rounded to tf32, padded stride ----
    #pragma unroll
    for (int i = 0; i < (D * D) / 256; i++) {       // 64 iters
        int idx = i * 256 + tid;
        float w = W[idx];
        unsigned t;
        asm("cvt.rna.tf32.f32 %0, %1;" : "=r"(t) : "f"(w));
        Ws[(idx >> 7) * WS_STRIDE + (idx & 127)] = __uint_as_float(t);
    }
    __syncthreads();

    const int warp = tid >> 5;
    const int lane = tid & 31;
    const int gid  = lane >> 2;     // 0..7
    const int c    = lane & 3;      // 0..3

    const int row0 = blockIdx.x * 128 + warp * 16;
    const int rA = row0 + gid;          // rows gid, gid+8 of the 16-row tile
    const int rB = row0 + gid + 8;
    const int rAc = min(rA, N_USERS - 1);
    const int rBc = min(rB, N_USERS - 1);
    const float* __restrict__ pA = emb + (size_t)rAc * D;
    const float* __restrict__ pB = emb + (size_t)rBc * D;

    float acc[16][4];
    #pragma unroll
    for (int j = 0; j < 16; j++)
        #pragma unroll
        for (int q = 0; q < 4; q++) acc[j][q] = 0.f;

    #pragma unroll 1
    for (int kk = 0; kk < 16; kk++) {
        const int k0 = kk * 8;
        // A fragment (m16k8 row-major): a0=[gid][c] a1=[gid+8][c] a2=[gid][c+4] a3=[gid+8][c+4]
        float a0f = pA[k0 + c];
        float a1f = pB[k0 + c];
        float a2f = pA[k0 + c + 4];
        float a3f = pB[k0 + c + 4];
        unsigned a0, a1, a2, a3;
        asm("cvt.rna.tf32.f32 %0, %1;" : "=r"(a0) : "f"(a0f));
        asm("cvt.rna.tf32.f32 %0, %1;" : "=r"(a1) : "f"(a1f));
        asm("cvt.rna.tf32.f32 %0, %1;" : "=r"(a2) : "f"(a2f));
        asm("cvt.rna.tf32.f32 %0, %1;" : "=r"(a3) : "f"(a3f));

        const float* wr0 = Ws + (k0 + c) * WS_STRIDE + gid;       // b0 row
        const float* wr1 = Ws + (k0 + c + 4) * WS_STRIDE + gid;   // b1 row

        #pragma unroll
        for (int j = 0; j < 16; j++) {
            // B fragment (k8n8 col-major): b0=[c][n0+gid] b1=[c+4][n0+gid]
            unsigned b0 = __float_as_uint(wr0[j * 8]);
            unsigned b1 = __float_as_uint(wr1[j * 8]);
            asm volatile(
                "mma.sync.aligned.m16n8k8.row.col.f32.tf32.tf32.f32 "
                "{%0,%1,%2,%3}, {%4,%5,%6,%7}, {%8,%9}, {%0,%1,%2,%3};"
                : "+f"(acc[j][0]), "+f"(acc[j][1]), "+f"(acc[j][2]), "+f"(acc[j][3])
                : "r"(a0), "r"(a1), "r"(a2), "r"(a3), "r"(b0), "r"(b1));
        }
    }

    // ---- epilogue: fp16 weighted. d0/d1 = row gid cols {2c,2c+1}; d2/d3 row gid+8 ----
    #pragma unroll
    for (int j = 0; j < 16; j++) {
        const int col = j * 8 + 2 * c;
        __half2 hA = __floats2half2_rn(acc[j][0], acc[j][1]);
        __half2 hB = __floats2half2_rn(acc[j][2], acc[j][3]);
        if (rA < N_USERS) *reinterpret_cast<__half2*>(wout + (size_t)rA * D + col) = hA;
        if (rB < N_USERS) *reinterpret_cast<__half2*>(wout + (size_t)rB * D + col) = hB;
    }
}

// ---------------------------------------------------------------------------
// Kernel 2: out[rows[e]] += vals[e] * weighted_h[cols[e]]
// 8 edges per warp: MLP=8 gathers, then 8 REDs. 800000 = 100000*8, no tail.
// ---------------------------------------------------------------------------
__global__ __launch_bounds__(256) void edge_kernel(
    const int* __restrict__ rows,
    const int* __restrict__ cols,
    const float* __restrict__ vals,
    const __half* __restrict__ weighted,
    float* __restrict__ out)
{
    const int warp = (blockIdx.x * blockDim.x + threadIdx.x) >> 5;
    const int lane = threadIdx.x & 31;
    const long long e0 = (long long)warp * E_PER_WARP;
    if (e0 >= N_EDGES) return;

    const int eidx = (int)e0 + (lane & (E_PER_WARP - 1));
    int   ri = __ldg(rows + eidx);
    int   ci = __ldg(cols + eidx);
    float vi = __ldg(vals + eidx);

    uint2 pk[E_PER_WARP];
    #pragma unroll
    for (int i = 0; i < E_PER_WARP; i++) {
        int cc = __shfl_sync(0xffffffffu, ci, i);
        pk[i] = *reinterpret_cast<const uint2*>(weighted + (size_t)cc * D + lane * 4);
    }

    #pragma unroll
    for (int i = 0; i < E_PER_WARP; i++) {
        int   r = __shfl_sync(0xffffffffu, ri, i);
        float v = __shfl_sync(0xffffffffu, vi, i);
        __half2 h0 = *reinterpret_cast<__half2*>(&pk[i].x);
        __half2 h1 = *reinterpret_cast<__half2*>(&pk[i].y);
        float2 f0 = __half22float2(h0);
        float2 f1 = __half22float2(h1);
        float px = v * f0.x, py = v * f0.y, pz = v * f1.x, pw = v * f1.y;
        float* dst = out + (size_t)r * D + lane * 4;
        asm volatile("red.global.add.v4.f32 [%0], {%1,%2,%3,%4};"
                     :: "l"(dst), "f"(px), "f"(py), "f"(pz), "f"(pw)
                     : "memory");
    }
}

// ---------------------------------------------------------------------------
// Launch
// ---------------------------------------------------------------------------
extern "C" void kernel_launch(void* const* d_in, const int* in_sizes, int n_in,
                              void* d_out, int out_size)
{
    const float* user_emb = (const float*)d_in[0];
    const float* social_w = (const float*)d_in[1];
    const int*   rows     = (const int*)d_in[2];
    const int*   cols     = (const int*)d_in[3];
    const float* vals     = (const float*)d_in[4];
    float*       out      = (float*)d_out;

    __half* weighted = nullptr;
    cudaGetSymbolAddress((void**)&weighted, g_weighted_h);

    // 1. GEMM (tf32 tensor cores) + fused residual init
    {
        const int smem_bytes = D * WS_STRIDE * sizeof(float);   // 67584
        cudaFuncSetAttribute(gemm_kernel,
                             cudaFuncAttributeMaxDynamicSharedMemorySize, smem_bytes);
        int nblk = (N_USERS + 127) / 128;                       // 391
        gemm_kernel<<<nblk, 256, smem_bytes>>>(user_emb, social_w, weighted, out);
    }

    // 2. scatter-add edges, 8 edges per warp
    {
        int nwarps = N_EDGES / E_PER_WARP;              // 100000
        int nblk = (nwarps * 32 + 255) / 256;           // 12500
        edge_kernel<<<nblk, 256>>>(rows, cols, vals, weighted, out);
    }
}

// round 7
// speedup vs baseline: 2.0338x; 1.1205x over previous
#include <cuda_runtime.h>
#include <cuda_fp16.h>
#include <cstdint>

#define N_USERS 50000
#define D 128
#define N_EDGES 800000
#define E_PER_WARP 16
#define AS_STRIDE 132          // padded A smem stride in floats (conflict-free)

// -------- device scratch (no cudaMalloc allowed) --------
__device__ __half g_weighted_h[N_USERS * D];   // weighted = emb @ W in fp16
__device__ float2 g_wpack[16 * 16 * 32];       // W pre-packed into MMA B fragments

// ---------------------------------------------------------------------------
// Kernel 0: pack W into B-fragment order, tf32-rounded.
// Wp[(kk*16 + j)*32 + lane] = { W[8kk + c][8j + gid], W[8kk + c + 4][8j + gid] }
// with c = lane&3, gid = lane>>2.  (Matches m16n8k8.row.col B fragment.)
// ---------------------------------------------------------------------------
__global__ void pack_w_kernel(const float* __restrict__ W, float2* __restrict__ Wp)
{
    int idx = blockIdx.x * blockDim.x + threadIdx.x;
    if (idx >= 16 * 16 * 32) return;
    int lane = idx & 31;
    int j    = (idx >> 5) & 15;
    int kk   = idx >> 9;
    int c    = lane & 3;
    int gid  = lane >> 2;
    int col  = j * 8 + gid;
    float w0 = W[(kk * 8 + c) * D + col];
    float w1 = W[(kk * 8 + c + 4) * D + col];
    unsigned t0, t1;
    asm("cvt.rna.tf32.f32 %0, %1;" : "=r"(t0) : "f"(w0));
    asm("cvt.rna.tf32.f32 %0, %1;" : "=r"(t1) : "f"(w1));
    Wp[idx] = make_float2(__uint_as_float(t0), __uint_as_float(t1));
}

// ---------------------------------------------------------------------------
// Kernel 1: weighted_h = fp16(user_emb @ W) via tf32 mma.sync; out = user_emb.
// Block = 256 threads (8 warps), 128 rows per block.
// A tile staged in smem (padded stride), B fragments from packed smem copy.
// ---------------------------------------------------------------------------
__global__ __launch_bounds__(256) void gemm_kernel(
    const float* __restrict__ emb,
    const float2* __restrict__ Wp,  // packed B fragments (tf32 bits)
    __half* __restrict__ wout,      // [N_USERS, D] fp16
    float* __restrict__ resout)     // [N_USERS, D] fp32 residual init
{
    extern __shared__ float smemf[];
    float*  As  = smemf;                            // [128 * AS_STRIDE] floats
    float2* Wps = reinterpret_cast<float2*>(smemf + 128 * AS_STRIDE);  // [8192]

    const int tid = threadIdx.x;
    const int rowbase = blockIdx.x * 128;

    // ---- stage A tile (coalesced float4) + fused residual copy out = emb ----
    {
        const float4* src = reinterpret_cast<const float4*>(emb);
        float4* dst = reinterpret_cast<float4*>(resout);
        float4* As4 = reinterpret_cast<float4*>(As);
        #pragma unroll
        for (int i = 0; i < 16; i++) {              // 128 rows * 32 float4
            int idx = i * 256 + tid;
            int r = idx >> 5;                       // tile row
            int q = idx & 31;                       // float4 within row
            int gr = min(rowbase + r, N_USERS - 1);
            float4 v = src[(size_t)gr * 32 + q];
            As4[r * (AS_STRIDE / 4) + q] = v;       // stride 33 float4
            if (rowbase + r < N_USERS)
                dst[(size_t)(rowbase + r) * 32 + q] = v;
        }
    }

    // ---- stage packed W fragments (coalesced float4 over float2 pairs) ----
    {
        const float4* srcp = reinterpret_cast<const float4*>(Wp);
        float4* dstp = reinterpret_cast<float4*>(Wps);
        #pragma unroll
        for (int i = 0; i < 16; i++)                // 4096 float4
            dstp[i * 256 + tid] = srcp[i * 256 + tid];
    }
    __syncthreads();

    const int warp = tid >> 5;
    const int lane = tid & 31;
    const int gid  = lane >> 2;     // 0..7
    const int c    = lane & 3;      // 0..3

    const int trA = warp * 16 + gid;        // tile rows
    const int trB = warp * 16 + gid + 8;
    const int rA = rowbase + trA;
    const int rB = rowbase + trB;
    const float* pA = As + trA * AS_STRIDE;
    const float* pB = As + trB * AS_STRIDE;

    float acc[16][4];
    #pragma unroll
    for (int j = 0; j < 16; j++)
        #pragma unroll
        for (int q = 0; q < 4; q++) acc[j][q] = 0.f;

    #pragma unroll 1
    for (int kk = 0; kk < 16; kk++) {
        const int k0 = kk * 8;
        // A fragment (conflict-free: bank = (4*gid + c + 8kk) % 32, all distinct)
        float a0f = pA[k0 + c];
        float a1f = pB[k0 + c];
        float a2f = pA[k0 + c + 4];
        float a3f = pB[k0 + c + 4];
        unsigned a0, a1, a2, a3;
        asm("cvt.rna.tf32.f32 %0, %1;" : "=r"(a0) : "f"(a0f));
        asm("cvt.rna.tf32.f32 %0, %1;" : "=r"(a1) : "f"(a1f));
        asm("cvt.rna.tf32.f32 %0, %1;" : "=r"(a2) : "f"(a2f));
        asm("cvt.rna.tf32.f32 %0, %1;" : "=r"(a3) : "f"(a3f));

        const float2* wrow = Wps + kk * 16 * 32 + lane;
        #pragma unroll
        for (int j = 0; j < 16; j++) {
            float2 bp = wrow[j * 32];               // one LDS.64, conflict-free
            unsigned b0 = __float_as_uint(bp.x);
            unsigned b1 = __float_as_uint(bp.y);
            asm volatile(
                "mma.sync.aligned.m16n8k8.row.col.f32.tf32.tf32.f32 "
                "{%0,%1,%2,%3}, {%4,%5,%6,%7}, {%8,%9}, {%0,%1,%2,%3};"
                : "+f"(acc[j][0]), "+f"(acc[j][1]), "+f"(acc[j][2]), "+f"(acc[j][3])
                : "r"(a0), "r"(a1), "r"(a2), "r"(a3), "r"(b0), "r"(b1));
        }
    }

    // ---- epilogue: fp16 weighted ----
    #pragma unroll
    for (int j = 0; j < 16; j++) {
        const int col = j * 8 + 2 * c;
        __half2 hA = __floats2half2_rn(acc[j][0], acc[j][1]);
        __half2 hB = __floats2half2_rn(acc[j][2], acc[j][3]);
        if (rA < N_USERS) *reinterpret_cast<__half2*>(wout + (size_t)rA * D + col) = hA;
        if (rB < N_USERS) *reinterpret_cast<__half2*>(wout + (size_t)rB * D + col) = hB;
    }
}

// ---------------------------------------------------------------------------
// Kernel 2: out[rows[e]] += vals[e] * weighted_h[cols[e]]
// 16 edges per warp: lanes 0-15 hold metadata, 16 gathers in flight, 16 REDs.
// 800000 = 50000 warps * 16 exactly; no tail.
// ---------------------------------------------------------------------------
__global__ __launch_bounds__(256) void edge_kernel(
    const int* __restrict__ rows,
    const int* __restrict__ cols,
    const float* __restrict__ vals,
    const __half* __restrict__ weighted,
    float* __restrict__ out)
{
    const int warp = (blockIdx.x * blockDim.x + threadIdx.x) >> 5;
    const int lane = threadIdx.x & 31;
    const long long e0 = (long long)warp * E_PER_WARP;
    if (e0 >= N_EDGES) return;

    const int eidx = (int)e0 + (lane & (E_PER_WARP - 1));
    int   ri = __ldg(rows + eidx);
    int   ci = __ldg(cols + eidx);
    float vi = __ldg(vals + eidx);

    uint2 pk[E_PER_WARP];
    #pragma unroll
    for (int i = 0; i < E_PER_WARP; i++) {
        int cc = __shfl_sync(0xffffffffu, ci, i);
        pk[i] = *reinterpret_cast<const uint2*>(weighted + (size_t)cc * D + lane * 4);
    }

    #pragma unroll
    for (int i = 0; i < E_PER_WARP; i++) {
        int   r = __shfl_sync(0xffffffffu, ri, i);
        float v = __shfl_sync(0xffffffffu, vi, i);
        __half2 h0 = *reinterpret_cast<__half2*>(&pk[i].x);
        __half2 h1 = *reinterpret_cast<__half2*>(&pk[i].y);
        float2 f0 = __half22float2(h0);
        float2 f1 = __half22float2(h1);
        float px = v * f0.x, py = v * f0.y, pz = v * f1.x, pw = v * f1.y;
        float* dst = out + (size_t)r * D + lane * 4;
        asm volatile("red.global.add.v4.f32 [%0], {%1,%2,%3,%4};"
                     :: "l"(dst), "f"(px), "f"(py), "f"(pz), "f"(pw)
                     : "memory");
    }
}

// ---------------------------------------------------------------------------
// Launch
// ---------------------------------------------------------------------------
extern "C" void kernel_launch(void* const* d_in, const int* in_sizes, int n_in,
                              void* d_out, int out_size)
{
    const float* user_emb = (const float*)d_in[0];
    const float* social_w = (const float*)d_in[1];
    const int*   rows     = (const int*)d_in[2];
    const int*   cols     = (const int*)d_in[3];
    const float* vals     = (const float*)d_in[4];
    float*       out      = (float*)d_out;

    __half* weighted;  cudaGetSymbolAddress((void**)&weighted, g_weighted_h);
    float2* wpack;     cudaGetSymbolAddress((void**)&wpack,    g_wpack);

    // 0. pack W into B-fragment order (tiny)
    pack_w_kernel<<<32, 256>>>(social_w, wpack);

    // 1. GEMM (tf32 tensor cores) + fused residual init
    {
        const int smem_bytes = 128 * AS_STRIDE * sizeof(float)
                             + 16 * 16 * 32 * sizeof(float2);   // 67584 + 65536
        cudaFuncSetAttribute(gemm_kernel,
                             cudaFuncAttributeMaxDynamicSharedMemorySize, smem_bytes);
        int nblk = (N_USERS + 127) / 128;                       // 391
        gemm_kernel<<<nblk, 256, smem_bytes>>>(user_emb, wpack, weighted, out);
    }

    // 2. scatter-add edges, 16 edges per warp
    {
        int nwarps = N_EDGES / E_PER_WARP;              // 50000
        int nblk = (nwarps * 32 + 255) / 256;           // 6250
        edge_kernel<<<nblk, 256>>>(rows, cols, vals, weighted, out);
    }
}